// round 3
// baseline (speedup 1.0000x reference)
#include <cuda_runtime.h>

#define E_EDGES 250000
#define TILE_E  64
#define NBLOCKS ((E_EDGES + TILE_E - 1) / TILE_E)

using u64 = unsigned long long;

__device__ __forceinline__ u64 ffma2(u64 a, u64 b, u64 c) {
    u64 d;
    asm("fma.rn.f32x2 %0, %1, %2, %3;" : "=l"(d) : "l"(a), "l"(b), "l"(c));
    return d;
}
__device__ __forceinline__ u64 dup2(float x) {
    u64 d;
    asm("mov.b64 %0, {%1, %1};" : "=l"(d) : "f"(x));
    return d;
}
__device__ __forceinline__ float lo32(u64 v) { return __uint_as_float((unsigned)(v & 0xffffffffu)); }
__device__ __forceinline__ float hi32(u64 v) { return __uint_as_float((unsigned)(v >> 32)); }

// Shared layout (bytes):
//   wsh  : float2[64][3][32]  [0, 49152)       {w[2cg][r], w[2cg+1][r]} per (d,r,cg)
//   invs : float [64][65]     [49152, 65792)   pad-65 rows -> conflict-free STS
//   shs  : float [64*9]       [65792, 68096)
#define SMEM_BYTES 68096

__global__ __launch_bounds__(256, 3)
void sh_tensor_embed_kernel(const float* __restrict__ vec,
                            const float* __restrict__ inv,
                            const float* __restrict__ W,
                            float* __restrict__ out) {
    extern __shared__ char sm[];
    float2* wsh  = (float2*)(sm);
    float*  invs = (float*) (sm + 49152);
    float*  shs  = (float*) (sm + 65792);

    const int tid = threadIdx.x;
    const int e0  = blockIdx.x * TILE_E;

    // ---- fill W tile as channel-pairs: wsh[(d*3+r)*32 + cg] = {W[d][6cg+r], W[d][6cg+3+r]} ----
    for (int idx = tid; idx < 64 * 3 * 32; idx += 256) {
        int cg = idx & 31;
        int dr = idx >> 5;          // d*3 + r
        int d  = dr / 3, r = dr - 3 * d;
        const float* g = W + d * 192 + 6 * cg + r;
        wsh[idx] = make_float2(g[0], g[3]);
    }
    // ---- fill edge-invariant tile (transposed, pad 65) ----
    for (int idx = tid; idx < TILE_E * 64; idx += 256) {
        int el = idx >> 6, d = idx & 63;
        int e = e0 + el; if (e >= E_EDGES) e = E_EDGES - 1;
        invs[d * 65 + el] = inv[(size_t)e * 64 + d];
    }
    // ---- spherical harmonics per edge ----
    if (tid < TILE_E) {
        int e = e0 + tid; if (e >= E_EDGES) e = E_EDGES - 1;
        float x = vec[(size_t)e * 3 + 0];
        float y = vec[(size_t)e * 3 + 1];
        float z = vec[(size_t)e * 3 + 2];
        float r = rsqrtf(x * x + y * y + z * z);
        x *= r; y *= r; z *= r;
        const float s3  = 1.7320508075688772f;   // sqrt(3)
        const float s5  = 2.2360679774997896f;   // sqrt(5)
        const float s15 = 3.8729833462074170f;   // sqrt(15)
        float* o = shs + tid * 9;
        o[0] = 1.0f;
        o[1] = s3 * x;
        o[2] = s3 * y;
        o[3] = s3 * z;
        o[4] = s15 * x * z;
        o[5] = s15 * x * y;
        o[6] = s5 * (y * y - 0.5f * (x * x + z * z));
        o[7] = s15 * y * z;
        o[8] = 0.5f * s15 * (z * z - x * x);
    }
    __syncthreads();

    // thread tile: 1 channel-pair (channels 2cg, 2cg+1) x 8 edges
    const int cg = tid & 31;
    const int eg = tid >> 5;          // warp id -> edges eg*8 .. eg*8+7 (warp-uniform)

    u64 acc[8][3];
    #pragma unroll
    for (int j = 0; j < 8; j++)
        #pragma unroll
        for (int r = 0; r < 3; r++)
            acc[j][r] = 0ull;

    const float2* wp  = wsh + cg;
    const float*  ivp = invs + eg * 8;

    #pragma unroll 2
    for (int d = 0; d < 64; d++) {
        u64 wv[3];
        #pragma unroll
        for (int r = 0; r < 3; r++)
            wv[r] = *(const u64*)&wp[(d * 3 + r) * 32];   // conflict-free LDS.64
        #pragma unroll
        for (int j = 0; j < 8; j++) {
            u64 pv = dup2(ivp[d * 65 + j]);               // broadcast LDS.32 + dup
            #pragma unroll
            for (int r = 0; r < 3; r++)
                acc[j][r] = ffma2(pv, wv[r], acc[j][r]);
        }
    }

    // ---- epilogue: out[e][c][k] = sh[k] * w[c][widx[k]]; 18 contiguous floats per edge ----
    #pragma unroll
    for (int j = 0; j < 8; j++) {
        int el = eg * 8 + j;
        int e  = e0 + el;
        if (e < E_EDGES) {
            const float* shp = shs + el * 9;
            float shv[9];
            #pragma unroll
            for (int k = 0; k < 9; k++) shv[k] = shp[k];
            float w0[3], w1[3];
            #pragma unroll
            for (int r = 0; r < 3; r++) {
                w0[r] = lo32(acc[j][r]);   // channel 2cg
                w1[r] = hi32(acc[j][r]);   // channel 2cg+1
            }
            float vals[18];
            #pragma unroll
            for (int k = 0; k < 9; k++) {
                int r = (k == 0) ? 0 : ((k < 4) ? 1 : 2);
                vals[k]     = shv[k] * w0[r];
                vals[9 + k] = shv[k] * w1[r];
            }
            float2* p = (float2*)(out + (size_t)e * 576 + cg * 18);
            #pragma unroll
            for (int q = 0; q < 9; q++)
                p[q] = make_float2(vals[2 * q], vals[2 * q + 1]);
        }
    }
}

extern "C" void kernel_launch(void* const* d_in, const int* in_sizes, int n_in,
                              void* d_out, int out_size) {
    const float* vec = nullptr;
    const float* inv = nullptr;
    const float* W   = nullptr;
    for (int i = 0; i < n_in; i++) {
        if      (in_sizes[i] == E_EDGES * 3)  vec = (const float*)d_in[i];
        else if (in_sizes[i] == E_EDGES * 64) inv = (const float*)d_in[i];
        else if (in_sizes[i] == 64 * 192)     W   = (const float*)d_in[i];
    }
    cudaFuncSetAttribute(sh_tensor_embed_kernel,
                         cudaFuncAttributeMaxDynamicSharedMemorySize, SMEM_BYTES);
    sh_tensor_embed_kernel<<<NBLOCKS, 256, SMEM_BYTES>>>(vec, inv, W, (float*)d_out);
}

// round 4
// speedup vs baseline: 1.5990x; 1.5990x over previous
#include <cuda_runtime.h>

#define E_EDGES 250000
#define TILE_E  64
#define NBLOCKS ((E_EDGES + TILE_E - 1) / TILE_E)

using u64 = unsigned long long;

__device__ __forceinline__ u64 ffma2(u64 a, u64 b, u64 c) {
    u64 d;
    asm("fma.rn.f32x2 %0, %1, %2, %3;" : "=l"(d) : "l"(a), "l"(b), "l"(c));
    return d;
}
__device__ __forceinline__ u64 dup2(float x) {
    u64 d;
    asm("mov.b64 %0, {%1, %1};" : "=l"(d) : "f"(x));
    return d;
}

// Shared layout (bytes):
//   wsh  : float2[64*3*32] [0, 49152)        {W[d][6cg+r], W[d][6cg+3+r]}
//   invs : float [64*68]   [49152, 66560)    row stride 68 -> aligned LDS.128 reads
//   shs  : float [64*9]    [66560, 68864)
//   wout : float [64*198]  overlay [0,50688) (wsh/invs dead after mainloop)
//          per edge: w[c][r] at el*198 + r*66 + c
#define SMEM_BYTES 68864

__global__ __launch_bounds__(256, 3)
void sh_tensor_embed_kernel(const float* __restrict__ vec,
                            const float* __restrict__ inv,
                            const float* __restrict__ W,
                            float* __restrict__ out) {
    extern __shared__ char sm[];
    float2* wsh  = (float2*)(sm);
    float*  invs = (float*) (sm + 49152);
    float*  shs  = (float*) (sm + 66560);
    float*  wout = (float*) (sm);            // overlay

    const int tid = threadIdx.x;
    const int e0  = blockIdx.x * TILE_E;

    // ---- fill W tile as channel-pairs: wsh[(d*3+r)*32+cg] = {W[d][6cg+r], W[d][6cg+3+r]} ----
    for (int idx = tid; idx < 64 * 3 * 32; idx += 256) {
        int cg = idx & 31;
        int dr = idx >> 5;
        int d  = dr / 3, r = dr - 3 * d;
        const float* g = W + d * 192 + 6 * cg + r;
        wsh[idx] = make_float2(g[0], g[3]);
    }
    // ---- fill edge-invariant tile (transposed, stride 68) ----
    for (int idx = tid; idx < TILE_E * 64; idx += 256) {
        int el = idx >> 6, d = idx & 63;
        int e = e0 + el; if (e >= E_EDGES) e = E_EDGES - 1;
        invs[d * 68 + el] = inv[(size_t)e * 64 + d];
    }
    // ---- spherical harmonics per edge ----
    if (tid < TILE_E) {
        int e = e0 + tid; if (e >= E_EDGES) e = E_EDGES - 1;
        float x = vec[(size_t)e * 3 + 0];
        float y = vec[(size_t)e * 3 + 1];
        float z = vec[(size_t)e * 3 + 2];
        float r = rsqrtf(x * x + y * y + z * z);
        x *= r; y *= r; z *= r;
        const float s3  = 1.7320508075688772f;   // sqrt(3)
        const float s5  = 2.2360679774997896f;   // sqrt(5)
        const float s15 = 3.8729833462074170f;   // sqrt(15)
        float* o = shs + tid * 9;
        o[0] = 1.0f;
        o[1] = s3 * x;
        o[2] = s3 * y;
        o[3] = s3 * z;
        o[4] = s15 * x * z;
        o[5] = s15 * x * y;
        o[6] = s5 * (y * y - 0.5f * (x * x + z * z));
        o[7] = s15 * y * z;
        o[8] = 0.5f * s15 * (z * z - x * x);
    }
    __syncthreads();

    const int lane = tid & 31;
    const int eg   = tid >> 5;        // warp id -> edges eg*8 .. eg*8+7

    // ---- mainloop: channels {2*lane, 2*lane+1}, 8 edges ----
    u64 acc[8][3];
    #pragma unroll
    for (int j = 0; j < 8; j++)
        #pragma unroll
        for (int r = 0; r < 3; r++)
            acc[j][r] = 0ull;

    const float2* wp = wsh + lane;
    const float*  ip = invs + eg * 8;

    #pragma unroll 2
    for (int d = 0; d < 64; d++) {
        u64 wv[3];
        #pragma unroll
        for (int r = 0; r < 3; r++)
            wv[r] = *(const u64*)(wp + (d * 3 + r) * 32);   // LDS.64, conflict-free
        float iv[8];
        *(float4*)&iv[0] = *(const float4*)(ip + d * 68);       // broadcast LDS.128
        *(float4*)&iv[4] = *(const float4*)(ip + d * 68 + 4);   // broadcast LDS.128
        #pragma unroll
        for (int j = 0; j < 8; j++) {
            u64 pv = dup2(iv[j]);
            #pragma unroll
            for (int r = 0; r < 3; r++)
                acc[j][r] = ffma2(pv, wv[r], acc[j][r]);
        }
    }

    // ---- stage w to smem (warp-local transpose) ----
    __syncthreads();          // everyone done reading wsh/invs before overlay write
    #pragma unroll
    for (int j = 0; j < 8; j++) {
        int el = eg * 8 + j;
        #pragma unroll
        for (int r = 0; r < 3; r++)
            *(u64*)(wout + el * 198 + r * 66 + 2 * lane) = acc[j][r];  // STS.64, conflict-free
    }
    __syncwarp();             // reader warp == writer warp

    // ---- coalesced epilogue: lane-major float4 stores ----
    #pragma unroll
    for (int q = 0; q < 5; q++) {
        int idx4 = q * 32 + lane;             // float4 index within the 576-float row
        bool act = idx4 < 144;
        int woff[4], koff[4];
        #pragma unroll
        for (int m = 0; m < 4; m++) {
            int idx = idx4 * 4 + m;
            int c = (idx * 14564) >> 17;      // exact idx/9 for this range
            int k = idx - c * 9;
            int r = (k == 0) ? 0 : ((k < 4) ? 1 : 2);
            woff[m] = r * 66 + c;
            koff[m] = k;
        }
        #pragma unroll
        for (int j = 0; j < 8; j++) {
            int el = eg * 8 + j;
            int e  = e0 + el;
            if (act && e < E_EDGES) {
                const float* wb = wout + el * 198;
                const float* sb = shs  + el * 9;
                float4 v;
                v.x = sb[koff[0]] * wb[woff[0]];
                v.y = sb[koff[1]] * wb[woff[1]];
                v.z = sb[koff[2]] * wb[woff[2]];
                v.w = sb[koff[3]] * wb[woff[3]];
                *(float4*)(out + (size_t)e * 576 + idx4 * 4) = v;   // coalesced STG.128
            }
        }
    }
}

extern "C" void kernel_launch(void* const* d_in, const int* in_sizes, int n_in,
                              void* d_out, int out_size) {
    const float* vec = nullptr;
    const float* inv = nullptr;
    const float* W   = nullptr;
    for (int i = 0; i < n_in; i++) {
        if      (in_sizes[i] == E_EDGES * 3)  vec = (const float*)d_in[i];
        else if (in_sizes[i] == E_EDGES * 64) inv = (const float*)d_in[i];
        else if (in_sizes[i] == 64 * 192)     W   = (const float*)d_in[i];
    }
    cudaFuncSetAttribute(sh_tensor_embed_kernel,
                         cudaFuncAttributeMaxDynamicSharedMemorySize, SMEM_BYTES);
    sh_tensor_embed_kernel<<<NBLOCKS, 256, SMEM_BYTES>>>(vec, inv, W, (float*)d_out);
}

// round 5
// speedup vs baseline: 1.6185x; 1.0122x over previous
#include <cuda_runtime.h>

#define E_EDGES 250000
#define TILE_E  64
#define NBLOCKS ((E_EDGES + TILE_E - 1) / TILE_E)

using u64 = unsigned long long;

__device__ __forceinline__ u64 ffma2(u64 a, u64 b, u64 c) {
    u64 d;
    asm("fma.rn.f32x2 %0, %1, %2, %3;" : "=l"(d) : "l"(a), "l"(b), "l"(c));
    return d;
}
__device__ __forceinline__ u64 dup2(float x) {
    u64 d;
    asm("mov.b64 %0, {%1, %1};" : "=l"(d) : "f"(x));
    return d;
}
__device__ __forceinline__ float lo32(u64 v) { return __uint_as_float((unsigned)(v & 0xffffffffu)); }
__device__ __forceinline__ float hi32(u64 v) { return __uint_as_float((unsigned)(v >> 32)); }

// Shared layout (bytes):
//   wsh  : float2[64*3*32] [0, 49152)      {W[d][6cg+r], W[d][6cg+3+r]} per (d,r,cg)
//   invs : float [64*68]   [49152, 66560)  stride-68 rows -> aligned LDS.128 in mainloop
//   shs  : float [64*9]    [66560, 68864)
//   stage: overlay [0, 37376)  per-warp 2 rows x 584 words (output-order staging)
#define SMEM_BYTES 68864

__global__ __launch_bounds__(256, 3)
void sh_tensor_embed_kernel(const float* __restrict__ vec,
                            const float* __restrict__ inv,
                            const float* __restrict__ W,
                            float* __restrict__ out) {
    extern __shared__ char sm[];
    float*  smf  = (float*)sm;
    float*  invs = (float*)(sm + 49152);
    float*  shs  = (float*)(sm + 66560);

    const int tid = threadIdx.x;
    const int e0  = blockIdx.x * TILE_E;

    // ---- W fill: coalesced LDG.128, scatter STS.32 into swizzled layout ----
    // wsh element: word ((d*3+r)*32+cg)*2 + h holds W[d][(2cg+h)*3 + r]
    for (int idx4 = tid; idx4 < 3072; idx4 += 256) {
        float4 v = ((const float4*)W)[idx4];
        int linear = idx4 * 4;
        int d    = linear / 192;
        int base = linear - d * 192;
        float vv[4] = {v.x, v.y, v.z, v.w};
        #pragma unroll
        for (int m = 0; m < 4; m++) {
            int col = base + m;
            int c = col / 3;
            int r = col - c * 3;
            int cg = c >> 1, h = c & 1;
            smf[((d * 3 + r) * 32 + cg) * 2 + h] = vv[m];
        }
    }
    // ---- edge-invariant tile (transposed, stride 68) ----
    for (int idx = tid; idx < TILE_E * 64; idx += 256) {
        int el = idx >> 6, d = idx & 63;
        int e = e0 + el; if (e >= E_EDGES) e = E_EDGES - 1;
        invs[d * 68 + el] = inv[(size_t)e * 64 + d];
    }
    // ---- spherical harmonics per edge ----
    if (tid < TILE_E) {
        int e = e0 + tid; if (e >= E_EDGES) e = E_EDGES - 1;
        float x = vec[(size_t)e * 3 + 0];
        float y = vec[(size_t)e * 3 + 1];
        float z = vec[(size_t)e * 3 + 2];
        float r = rsqrtf(x * x + y * y + z * z);
        x *= r; y *= r; z *= r;
        const float s3  = 1.7320508075688772f;
        const float s5  = 2.2360679774997896f;
        const float s15 = 3.8729833462074170f;
        float* o = shs + tid * 9;
        o[0] = 1.0f;
        o[1] = s3 * x;
        o[2] = s3 * y;
        o[3] = s3 * z;
        o[4] = s15 * x * z;
        o[5] = s15 * x * y;
        o[6] = s5 * (y * y - 0.5f * (x * x + z * z));
        o[7] = s15 * y * z;
        o[8] = 0.5f * s15 * (z * z - x * x);
    }
    __syncthreads();

    const int lane = tid & 31;
    const int eg   = tid >> 5;

    // ---- mainloop: channels {2*lane, 2*lane+1}, 8 edges ----
    u64 acc[8][3];
    #pragma unroll
    for (int j = 0; j < 8; j++)
        #pragma unroll
        for (int r = 0; r < 3; r++)
            acc[j][r] = 0ull;

    const float2* wp = (const float2*)sm + lane;
    const float*  ip = invs + eg * 8;

    #pragma unroll 2
    for (int d = 0; d < 64; d++) {
        u64 wv[3];
        #pragma unroll
        for (int r = 0; r < 3; r++)
            wv[r] = *(const u64*)(wp + (d * 3 + r) * 32);       // LDS.64, conflict-free
        float iv[8];
        *(float4*)&iv[0] = *(const float4*)(ip + d * 68);       // broadcast LDS.128
        *(float4*)&iv[4] = *(const float4*)(ip + d * 68 + 4);
        #pragma unroll
        for (int j = 0; j < 8; j++) {
            u64 pv = dup2(iv[j]);
            #pragma unroll
            for (int r = 0; r < 3; r++)
                acc[j][r] = ffma2(pv, wv[r], acc[j][r]);
        }
    }

    // ---- epilogue: owner thread writes FINAL values in output order to stage,
    //      then the same warp copies rows out coalesced ----
    __syncthreads();                         // wsh/invs dead -> overlay safe
    float* stage = smf + eg * (2 * 584);     // per-warp region, 2 rows x 584 words

    #pragma unroll
    for (int s = 0; s < 4; s++) {
        #pragma unroll
        for (int t = 0; t < 2; t++) {
            int j  = s * 2 + t;
            int el = eg * 8 + j;
            const float* sb = shs + el * 9;
            float sv[9];
            #pragma unroll
            for (int k = 0; k < 9; k++) sv[k] = sb[k];           // broadcast LDS
            float wa[3], wb[3];
            #pragma unroll
            for (int r = 0; r < 3; r++) { wa[r] = lo32(acc[j][r]); wb[r] = hi32(acc[j][r]); }
            float v[18];
            #pragma unroll
            for (int k = 0; k < 9; k++) {
                int r = (k == 0) ? 0 : ((k < 4) ? 1 : 2);
                v[k]     = sv[k] * wa[r];                        // channel 2*lane
                v[9 + k] = sv[k] * wb[r];                        // channel 2*lane+1
            }
            float* rowp = stage + t * 584 + lane * 18;           // contiguous 18 floats
            #pragma unroll
            for (int p = 0; p < 9; p++)
                *(float2*)(rowp + 2 * p) = make_float2(v[2 * p], v[2 * p + 1]);
        }
        __syncwarp();
        #pragma unroll
        for (int t = 0; t < 2; t++) {
            int el = eg * 8 + s * 2 + t;
            int e  = e0 + el;
            const float* rowp = stage + t * 584;
            if (e < E_EDGES) {
                #pragma unroll
                for (int q = 0; q < 5; q++) {
                    int idx4 = q * 32 + lane;
                    if (idx4 < 144) {
                        float4 val = *(const float4*)(rowp + idx4 * 4);   // coalesced LDS.128
                        *(float4*)(out + (size_t)e * 576 + idx4 * 4) = val; // coalesced STG.128
                    }
                }
            }
        }
        __syncwarp();
    }
}

extern "C" void kernel_launch(void* const* d_in, const int* in_sizes, int n_in,
                              void* d_out, int out_size) {
    const float* vec = nullptr;
    const float* inv = nullptr;
    const float* W   = nullptr;
    for (int i = 0; i < n_in; i++) {
        if      (in_sizes[i] == E_EDGES * 3)  vec = (const float*)d_in[i];
        else if (in_sizes[i] == E_EDGES * 64) inv = (const float*)d_in[i];
        else if (in_sizes[i] == 64 * 192)     W   = (const float*)d_in[i];
    }
    cudaFuncSetAttribute(sh_tensor_embed_kernel,
                         cudaFuncAttributeMaxDynamicSharedMemorySize, SMEM_BYTES);
    sh_tensor_embed_kernel<<<NBLOCKS, 256, SMEM_BYTES>>>(vec, inv, W, (float*)d_out);
}

// round 6
// speedup vs baseline: 1.7873x; 1.1043x over previous
#include <cuda_runtime.h>

#define E_EDGES 250000
#define TILE_E  64
#define NBLOCKS ((E_EDGES + TILE_E - 1) / TILE_E)

using u64 = unsigned long long;

__device__ float g_wsh[12288];   // pre-swizzled W image (exact smem layout)

__device__ __forceinline__ u64 ffma2(u64 a, u64 b, u64 c) {
    u64 d;
    asm("fma.rn.f32x2 %0, %1, %2, %3;" : "=l"(d) : "l"(a), "l"(b), "l"(c));
    return d;
}
__device__ __forceinline__ u64 dup2(float x) {
    u64 d;
    asm("mov.b64 %0, {%1, %1};" : "=l"(d) : "f"(x));
    return d;
}
__device__ __forceinline__ float lo32(u64 v) { return __uint_as_float((unsigned)(v & 0xffffffffu)); }
__device__ __forceinline__ float hi32(u64 v) { return __uint_as_float((unsigned)(v >> 32)); }

// g_wsh word ((d*3+r)*32 + pg)*2 + b = W[d][ (2*pg+b)*3 + r ]   (pg = channel-pair 0..31)
__global__ void prep_w_kernel(const float* __restrict__ W) {
    int o = blockIdx.x * 256 + threadIdx.x;
    if (o < 12288) {
        int b  = o & 1;
        int pg = (o >> 1) & 31;
        int dr = o >> 6;
        int d  = dr / 3, r = dr - 3 * d;
        g_wsh[o] = W[d * 192 + (2 * pg + b) * 3 + r];
    }
}

// Shared layout (bytes):
//   wsh  : float2[64*3*32] [0, 49152)      pair {W[2pg+0], W[2pg+1]} per (d,r,pg)
//   invs : float [64*68]   [49152, 66560)  d-major rows, stride 68
//   shs  : float [64*12]   [66560, 69632)  pad-12 rows -> LDS.128 sh reads
//   stage: overlay [0, 18688)  per-warp 2 rows x 292 words (output-order, warp-private)
#define SMEM_BYTES 69632

__global__ __launch_bounds__(256, 3)
void sh_tensor_embed_kernel(const float* __restrict__ vec,
                            const float* __restrict__ inv,
                            float* __restrict__ out) {
    extern __shared__ char sm[];
    float* smf  = (float*)sm;
    float* invs = (float*)(sm + 49152);
    float* shs  = (float*)(sm + 66560);

    const int tid = threadIdx.x;
    const int e0  = blockIdx.x * TILE_E;

    // ---- W fill: linear conflict-free copy of pre-swizzled image ----
    #pragma unroll
    for (int it = 0; it < 12; it++) {
        int idx = it * 256 + tid;
        ((float4*)smf)[idx] = ((const float4*)g_wsh)[idx];
    }
    // ---- edge-invariant tile (transposed, stride 68) ----
    for (int idx = tid; idx < TILE_E * 64; idx += 256) {
        int el = idx >> 6, d = idx & 63;
        int e = e0 + el; if (e >= E_EDGES) e = E_EDGES - 1;
        invs[d * 68 + el] = inv[(size_t)e * 64 + d];
    }
    // ---- spherical harmonics per edge (rows padded to 12) ----
    if (tid < TILE_E) {
        int e = e0 + tid; if (e >= E_EDGES) e = E_EDGES - 1;
        float x = vec[(size_t)e * 3 + 0];
        float y = vec[(size_t)e * 3 + 1];
        float z = vec[(size_t)e * 3 + 2];
        float r = rsqrtf(x * x + y * y + z * z);
        x *= r; y *= r; z *= r;
        const float s3  = 1.7320508075688772f;
        const float s5  = 2.2360679774997896f;
        const float s15 = 3.8729833462074170f;
        float* o = shs + tid * 12;
        o[0] = 1.0f;
        o[1] = s3 * x;
        o[2] = s3 * y;
        o[3] = s3 * z;
        o[4] = s15 * x * z;
        o[5] = s15 * x * y;
        o[6] = s5 * (y * y - 0.5f * (x * x + z * z));
        o[7] = s15 * y * z;
        o[8] = 0.5f * s15 * (z * z - x * x);
    }
    __syncthreads();

    // warp tile: 32 channels (half h) x 16 edges (quarter g); lane = eh*16 + cp
    const int lane = tid & 31;
    const int wid  = tid >> 5;
    const int cp   = lane & 15;          // channel-pair within half
    const int eh   = lane >> 4;          // edge-octet within quarter
    const int h    = wid & 1;            // channel half: channels [32h, 32h+32)
    const int g    = wid >> 1;           // edge quarter: edges [16g, 16g+16)

    u64 acc[8][3];
    #pragma unroll
    for (int j = 0; j < 8; j++)
        #pragma unroll
        for (int r = 0; r < 3; r++)
            acc[j][r] = 0ull;

    const float2* wp = (const float2*)smf + (h * 16 + cp);
    const float*  ip = invs + g * 16 + eh * 8;

    #pragma unroll 2
    for (int d = 0; d < 64; d++) {
        u64 wv[3];
        #pragma unroll
        for (int r = 0; r < 3; r++)
            wv[r] = *(const u64*)(wp + (d * 3 + r) * 32);   // 16 addrs x2 bcast = 1 phase
        float iv[8];
        *(float4*)&iv[0] = *(const float4*)(ip + d * 68);   // 2-addr broadcast LDS.128
        *(float4*)&iv[4] = *(const float4*)(ip + d * 68 + 4);
        #pragma unroll
        for (int j = 0; j < 8; j++) {
            u64 pv = dup2(iv[j]);
            #pragma unroll
            for (int r = 0; r < 3; r++)
                acc[j][r] = ffma2(pv, wv[r], acc[j][r]);
        }
    }

    // ---- epilogue: warp-private; warp's out slice per edge = contiguous 288 floats ----
    __syncthreads();                       // wsh reads done before overlay write
    float* stage = smf + wid * 584;        // 2 rows x 292 words, warp-private

    #pragma unroll
    for (int s = 0; s < 8; s++) {
        int el = g * 16 + eh * 8 + s;      // this lane's staged edge
        const float* sb = shs + el * 12;
        float4 sa = *(const float4*)sb;
        float4 sbv = *(const float4*)(sb + 4);
        float  s8 = sb[8];
        float sv[9] = {sa.x, sa.y, sa.z, sa.w, sbv.x, sbv.y, sbv.z, sbv.w, s8};
        float wa[3], wb[3];
        #pragma unroll
        for (int r = 0; r < 3; r++) { wa[r] = lo32(acc[s][r]); wb[r] = hi32(acc[s][r]); }
        float v[18];
        #pragma unroll
        for (int k = 0; k < 9; k++) {
            int r = (k == 0) ? 0 : ((k < 4) ? 1 : 2);
            v[k]     = sv[k] * wa[r];      // channel 32h + 2cp
            v[9 + k] = sv[k] * wb[r];      // channel 32h + 2cp + 1
        }
        float* rowp = stage + eh * 292 + cp * 18;
        #pragma unroll
        for (int p = 0; p < 9; p++)
            *(float2*)(rowp + 2 * p) = make_float2(v[2 * p], v[2 * p + 1]);
        __syncwarp();
        #pragma unroll
        for (int t = 0; t < 2; t++) {
            int e = e0 + g * 16 + t * 8 + s;
            if (e < E_EDGES) {
                const float4* src = (const float4*)(stage + t * 292);
                float4* dst = (float4*)(out + (size_t)e * 576 + h * 288);
                dst[lane]      = src[lane];          // 72 float4 per row, coalesced
                dst[lane + 32] = src[lane + 32];
                if (lane < 8) dst[lane + 64] = src[lane + 64];
            }
        }
        __syncwarp();
    }
}

extern "C" void kernel_launch(void* const* d_in, const int* in_sizes, int n_in,
                              void* d_out, int out_size) {
    const float* vec = nullptr;
    const float* inv = nullptr;
    const float* W   = nullptr;
    for (int i = 0; i < n_in; i++) {
        if      (in_sizes[i] == E_EDGES * 3)  vec = (const float*)d_in[i];
        else if (in_sizes[i] == E_EDGES * 64) inv = (const float*)d_in[i];
        else if (in_sizes[i] == 64 * 192)     W   = (const float*)d_in[i];
    }
    prep_w_kernel<<<48, 256>>>(W);
    cudaFuncSetAttribute(sh_tensor_embed_kernel,
                         cudaFuncAttributeMaxDynamicSharedMemorySize, SMEM_BYTES);
    sh_tensor_embed_kernel<<<NBLOCKS, 256, SMEM_BYTES>>>(vec, inv, (float*)d_out);
}